// round 8
// baseline (speedup 1.0000x reference)
#include <cuda_runtime.h>
#include <cuda_fp16.h>
#include <math.h>

#define NTOK 2048
#define DMODEL 2048
#define NH 32
#define NKV 8
#define HDIM 64
#define QD 2048
#define KD 512
#define NE 8
#define FF 7168
#define NROWS (2 * NTOK)
#define RMS_EPS 1e-5f

// ---------------- scratch (device globals) ----------------
// packed half2 planes: word(k2, ...) = (half at k=2*k2 in low 16, half at k=2*k2+1 in high 16)
__device__ unsigned g_hnp [2][NTOK * DMODEL / 2];
__device__ unsigned g_hn2p[2][NTOK * DMODEL / 2];
__device__ float    g_hn2f[NTOK * DMODEL];
__device__ float    g_q   [NTOK * QD];
__device__ float    g_k   [NTOK * KD];
__device__ float    g_v   [NTOK * KD];
__device__ unsigned g_qp  [2][NTOK * QD / 2];                 // [token][1024]
__device__ unsigned g_ktp [2][NKV * (HDIM / 2) * NTOK];       // [kvh][d2 32][t 2048]
__device__ unsigned g_vtp [2][NKV * (NTOK / 2) * HDIM];       // [kvh][t2 1024][d 64]
__device__ float    g_scores[134217728];                      // [h][q][t] 512MB
__device__ unsigned g_pp  [2][67108864];                      // [h][q][t2 1024]
__device__ unsigned g_attnp[2][NTOK * QD / 2];
__device__ float    g_h1  [NTOK * DMODEL];
__device__ float    g_comb[NTOK * NE];
__device__ int      g_cnt [NE];
__device__ int      g_off [NE];
__device__ int      g_idx [NE * NTOK];
__device__ int      g_tokexp[NTOK * 2];
__device__ int      g_tokpos[NTOK * 2];
__device__ float    g_act [NROWS * FF];
__device__ float    g_act2[NROWS * FF];
__device__ unsigned g_actcp[2][NROWS * FF / 2];
__device__ float    g_downc[NROWS * DMODEL];
// packed weights
__device__ unsigned g_wqp[2][(DMODEL / 2) * QD];
__device__ unsigned g_wkp[2][(DMODEL / 2) * KD];
__device__ unsigned g_wvp[2][(DMODEL / 2) * KD];
__device__ unsigned g_wop[2][(QD / 2) * DMODEL];
__device__ unsigned g_w1p[2][NE * (DMODEL / 2) * FF];
__device__ unsigned g_w3p[2][NE * (DMODEL / 2) * FF];
__device__ unsigned g_w2p[2][NE * (FF / 2) * DMODEL];

// ---------------- helpers ----------------
__device__ __forceinline__ void pack_planes(float a, float b, unsigned& wh, unsigned& wl) {
    __half ha = __float2half_rn(a), hb = __float2half_rn(b);
    __half la = __float2half_rn(a - __half2float(ha));
    __half lb = __float2half_rn(b - __half2float(hb));
    wh = (unsigned)__half_as_ushort(ha) | ((unsigned)__half_as_ushort(hb) << 16);
    wl = (unsigned)__half_as_ushort(la) | ((unsigned)__half_as_ushort(lb) << 16);
}

__device__ __forceinline__ void mma_f16(float* c, const unsigned* a, const unsigned* b) {
    asm volatile(
        "mma.sync.aligned.m16n8k16.row.col.f32.f16.f16.f32 "
        "{%0,%1,%2,%3}, {%4,%5,%6,%7}, {%8,%9}, {%0,%1,%2,%3};"
        : "+f"(c[0]), "+f"(c[1]), "+f"(c[2]), "+f"(c[3])
        : "r"(a[0]), "r"(a[1]), "r"(a[2]), "r"(a[3]), "r"(b[0]), "r"(b[1]));
}

// ---------------- weight split: fp32 [R][C] -> packed planes [R/2][C] ----------------
__global__ void split_kernel(const float* __restrict__ in, unsigned* __restrict__ oh,
                             unsigned* __restrict__ ol, int C) {
    int c = blockIdx.x * 256 + threadIdx.x;
    int r2 = blockIdx.y;
    float a = in[(size_t)(2 * r2) * C + c];
    float b = in[(size_t)(2 * r2 + 1) * C + c];
    unsigned wh, wl;
    pack_planes(a, b, wh, wl);
    oh[(size_t)r2 * C + c] = wh;
    ol[(size_t)r2 * C + c] = wl;
}

// ---------------- unified fp16x3 GEMM, 128x128 tile, 256 thr, 8 warps (64x32) ----------------
// MODE 0: QKV  (grid 24 x 16)       A=hnp,     out fp32 q/k/v
// MODE 1: O    (grid 16 x 16)       A=attnp,   out h1 = mma + hid
// MODE 2: GU   (grid 112 x 16 x 8)  A=hn2p[idx], out fp32 act/act2 compact
// MODE 3: DN   (grid 16 x 16 x 8)   A=actcp,   out fp32 downc compact
// MODE 4: S    (grid 16 x 16 x 32)  A=qp(head),B=ktp, out fp32 scores (causal skip)
// MODE 5: PV   (grid 1 x 16 x 32)   A=pp(head),B=vtp, out attnp planes
template <int MODE>
__global__ void __launch_bounds__(256)
gemmv2(const float* __restrict__ Rres) {
    const int by = blockIdx.y;
    const int bz = blockIdx.z;

    const unsigned* Ah;
    const unsigned* Al;
    const unsigned* Bh;
    const unsigned* Bl;
    float* Cf = nullptr;
    int N, K, rsA, ncol0 = blockIdx.x * 128, cnt = 0, off = 0;

    if (MODE == 0) {
        Ah = g_hnp[0]; Al = g_hnp[1]; rsA = DMODEL / 2; K = DMODEL;
        if (blockIdx.x < 16)      { Bh = g_wqp[0]; Bl = g_wqp[1]; Cf = g_q; N = QD; }
        else if (blockIdx.x < 20) { Bh = g_wkp[0]; Bl = g_wkp[1]; Cf = g_k; N = KD; ncol0 = (blockIdx.x - 16) * 128; }
        else                      { Bh = g_wvp[0]; Bl = g_wvp[1]; Cf = g_v; N = KD; ncol0 = (blockIdx.x - 20) * 128; }
    } else if (MODE == 1) {
        Ah = g_attnp[0]; Al = g_attnp[1]; rsA = QD / 2; K = QD;
        Bh = g_wop[0]; Bl = g_wop[1]; Cf = g_h1; N = DMODEL;
    } else if (MODE == 2) {
        cnt = g_cnt[bz];
        if (by * 128 >= cnt) return;
        off = g_off[bz];
        Ah = g_hn2p[0]; Al = g_hn2p[1]; rsA = DMODEL / 2; K = DMODEL; N = FF;
        size_t wo = (size_t)bz * (DMODEL / 2) * FF;
        if (blockIdx.x < 56) { Bh = g_w1p[0] + wo; Bl = g_w1p[1] + wo; Cf = g_act; }
        else                 { Bh = g_w3p[0] + wo; Bl = g_w3p[1] + wo; Cf = g_act2; ncol0 = (blockIdx.x - 56) * 128; }
    } else if (MODE == 3) {
        cnt = g_cnt[bz];
        if (by * 128 >= cnt) return;
        off = g_off[bz];
        Ah = g_actcp[0]; Al = g_actcp[1]; rsA = FF / 2; K = FF; N = DMODEL;
        size_t wo = (size_t)bz * (FF / 2) * DMODEL;
        Bh = g_w2p[0] + wo; Bl = g_w2p[1] + wo; Cf = g_downc;
    } else if (MODE == 4) {
        if (ncol0 >= by * 128 + 128) return;   // causal: whole block above diagonal
        Ah = g_qp[0] + bz * (HDIM / 2); Al = g_qp[1] + bz * (HDIM / 2);
        rsA = QD / 2; K = HDIM; N = NTOK;
        size_t wo = (size_t)(bz >> 2) * (HDIM / 2) * NTOK;
        Bh = g_ktp[0] + wo; Bl = g_ktp[1] + wo;
        Cf = g_scores + (size_t)bz * NTOK * NTOK;
    } else {  // MODE 5 PV
        size_t ao = (size_t)bz * NTOK * (NTOK / 2);
        Ah = g_pp[0] + ao; Al = g_pp[1] + ao;
        rsA = NTOK / 2; K = by * 128 + 128; N = HDIM;
        size_t wo = (size_t)(bz >> 2) * (NTOK / 2) * HDIM;
        Bh = g_vtp[0] + wo; Bl = g_vtp[1] + wo;
    }

    __shared__ unsigned As[2][2][8][136];   // [stage][plane][k2][row]
    __shared__ unsigned Bs[2][2][8][136];   // [stage][plane][k2][n]

    const int tid  = threadIdx.x;
    const int lane = tid & 31;
    const int wid  = tid >> 5;
    const int wm = (wid >> 2) * 64;
    const int wn = (wid & 3) * 32;
    const int lr = lane >> 2;
    const int lk = lane & 3;

    float acc[4][4][4];
#pragma unroll
    for (int i = 0; i < 4; i++)
#pragma unroll
        for (int j = 0; j < 4; j++)
#pragma unroll
            for (int q = 0; q < 4; q++) acc[i][j][q] = 0.f;

    // A loader: 256 thr = 128 rows x 2 k-halves
    const int arow = tid & 127;
    const int kh4  = (tid >> 7) * 4;
    size_t aoff;
    {
        int r0 = by * 128 + arow;
        if (MODE == 2) {
            int rr = r0 < cnt ? r0 : cnt - 1;
            aoff = (size_t)g_idx[bz * NTOK + rr] * rsA;
        } else if (MODE == 3) {
            int rr = r0 < cnt ? r0 : cnt - 1;
            aoff = (size_t)(off + rr) * rsA;
        } else {
            aoff = (size_t)r0 * rsA;
        }
    }
    // B loader: 8 k2-rows x 128 n / 256 thr
    const int k2r = tid >> 5;
    const int n4  = lane * 4;
    const bool bval = (MODE != 5) || (n4 < HDIM);

    const int niter = K / 16;
    uint4 rAh, rAl, rBh, rBl;
    const uint4 z4 = make_uint4(0, 0, 0, 0);

    // prologue: tile 0
    {
        rAh = *(const uint4*)(Ah + aoff + kh4);
        rAl = *(const uint4*)(Al + aoff + kh4);
        size_t boff = (size_t)k2r * N + ncol0 + n4;
        rBh = bval ? *(const uint4*)(Bh + boff) : z4;
        rBl = bval ? *(const uint4*)(Bl + boff) : z4;
        As[0][0][kh4 + 0][arow] = rAh.x; As[0][0][kh4 + 1][arow] = rAh.y;
        As[0][0][kh4 + 2][arow] = rAh.z; As[0][0][kh4 + 3][arow] = rAh.w;
        As[0][1][kh4 + 0][arow] = rAl.x; As[0][1][kh4 + 1][arow] = rAl.y;
        As[0][1][kh4 + 2][arow] = rAl.z; As[0][1][kh4 + 3][arow] = rAl.w;
        *(uint4*)&Bs[0][0][k2r][n4] = rBh;
        *(uint4*)&Bs[0][1][k2r][n4] = rBl;
    }
    __syncthreads();

    for (int it = 0; it < niter; it++) {
        const int cur = it & 1;
        if (it + 1 < niter) {
            int k0 = (it + 1) * 16;
            rAh = *(const uint4*)(Ah + aoff + (k0 >> 1) + kh4);
            rAl = *(const uint4*)(Al + aoff + (k0 >> 1) + kh4);
            size_t boff = (size_t)((k0 >> 1) + k2r) * N + ncol0 + n4;
            rBh = bval ? *(const uint4*)(Bh + boff) : z4;
            rBl = bval ? *(const uint4*)(Bl + boff) : z4;
        }
        // fragments
        unsigned afh[4][4], afl[4][4], bfh[4][2], bfl[4][2];
#pragma unroll
        for (int i = 0; i < 4; i++) {
            int r = wm + i * 16 + lr;
            afh[i][0] = As[cur][0][lk][r];
            afh[i][1] = As[cur][0][lk][r + 8];
            afh[i][2] = As[cur][0][lk + 4][r];
            afh[i][3] = As[cur][0][lk + 4][r + 8];
            afl[i][0] = As[cur][1][lk][r];
            afl[i][1] = As[cur][1][lk][r + 8];
            afl[i][2] = As[cur][1][lk + 4][r];
            afl[i][3] = As[cur][1][lk + 4][r + 8];
        }
#pragma unroll
        for (int j = 0; j < 4; j++) {
            int c = wn + j * 8 + lr;
            bfh[j][0] = Bs[cur][0][lk][c];
            bfh[j][1] = Bs[cur][0][lk + 4][c];
            bfl[j][0] = Bs[cur][1][lk][c];
            bfl[j][1] = Bs[cur][1][lk + 4][c];
        }
#pragma unroll
        for (int i = 0; i < 4; i++)
#pragma unroll
            for (int j = 0; j < 4; j++) {
                mma_f16(acc[i][j], afl[i], bfh[j]);
                mma_f16(acc[i][j], afh[i], bfl[j]);
                mma_f16(acc[i][j], afh[i], bfh[j]);
            }
        if (it + 1 < niter) {
            int nx = cur ^ 1;
            As[nx][0][kh4 + 0][arow] = rAh.x; As[nx][0][kh4 + 1][arow] = rAh.y;
            As[nx][0][kh4 + 2][arow] = rAh.z; As[nx][0][kh4 + 3][arow] = rAh.w;
            As[nx][1][kh4 + 0][arow] = rAl.x; As[nx][1][kh4 + 1][arow] = rAl.y;
            As[nx][1][kh4 + 2][arow] = rAl.z; As[nx][1][kh4 + 3][arow] = rAl.w;
            *(uint4*)&Bs[nx][0][k2r][n4] = rBh;
            *(uint4*)&Bs[nx][1][k2r][n4] = rBl;
            __syncthreads();
        }
    }

    // ---- epilogue ----
#pragma unroll
    for (int i = 0; i < 4; i++) {
#pragma unroll
        for (int j = 0; j < 4; j++) {
            int cc = ncol0 + wn + j * 8 + lk * 2;
#pragma unroll
            for (int half = 0; half < 2; half++) {
                int rg = by * 128 + wm + i * 16 + lr + half * 8;
                float v0 = acc[i][j][half * 2 + 0];
                float v1 = acc[i][j][half * 2 + 1];
                if (MODE == 0) {
                    *(float2*)&Cf[(size_t)rg * N + cc] = make_float2(v0, v1);
                } else if (MODE == 1) {
                    size_t o = (size_t)rg * N + cc;
                    *(float2*)&Cf[o] = make_float2(v0 + Rres[o], v1 + Rres[o + 1]);
                } else if (MODE == 2) {
                    if (rg < cnt)
                        *(float2*)&Cf[(size_t)(off + rg) * FF + cc] = make_float2(v0, v1);
                } else if (MODE == 3) {
                    if (rg < cnt)
                        *(float2*)&Cf[(size_t)(off + rg) * DMODEL + cc] = make_float2(v0, v1);
                } else if (MODE == 4) {
                    *(float2*)&Cf[(size_t)rg * NTOK + cc] = make_float2(v0, v1);
                } else {  // PV -> packed attn planes
                    if (cc < HDIM) {
                        unsigned wh, wl;
                        pack_planes(v0, v1, wh, wl);
                        size_t w = (size_t)rg * (QD / 2) + bz * (HDIM / 2) + (cc >> 1);
                        g_attnp[0][w] = wh;
                        g_attnp[1][w] = wl;
                    }
                }
            }
        }
    }
}

// ---------------- rmsnorm -> packed planes (+ optional fp32) ----------------
template <bool F32>
__global__ void rmsnorm_kernel(const float* __restrict__ x, const float* __restrict__ w,
                               unsigned* __restrict__ oh, unsigned* __restrict__ ol,
                               float* __restrict__ of) {
    int row = blockIdx.x;
    int tid = threadIdx.x;
    const float2* xr = (const float2*)(x + (size_t)row * DMODEL);
    float s = 0.f;
    for (int i = tid; i < DMODEL / 2; i += 256) {
        float2 v = xr[i];
        s += v.x * v.x + v.y * v.y;
    }
    for (int o = 16; o > 0; o >>= 1) s += __shfl_xor_sync(0xffffffffu, s, o);
    __shared__ float sh[8];
    if ((tid & 31) == 0) sh[tid >> 5] = s;
    __syncthreads();
    float tot = 0.f;
    for (int k = 0; k < 8; k++) tot += sh[k];
    float inv = rsqrtf(tot / (float)DMODEL + RMS_EPS);
    for (int i = tid; i < DMODEL / 2; i += 256) {
        float2 v = xr[i];
        float y0 = v.x * inv * w[2 * i];
        float y1 = v.y * inv * w[2 * i + 1];
        unsigned wh, wl;
        pack_planes(y0, y1, wh, wl);
        oh[(size_t)row * (DMODEL / 2) + i] = wh;
        ol[(size_t)row * (DMODEL / 2) + i] = wl;
        if (F32) *(float2*)&of[(size_t)row * DMODEL + 2 * i] = make_float2(y0, y1);
    }
}

// ---------------- RoPE: q fp32 -> qp packed ----------------
__global__ void rope_q_kernel(const int* __restrict__ pos) {
    int s = blockIdx.x;
    int h = threadIdx.x >> 5, i = threadIdx.x & 31;
    float p = (float)pos[s];
    float inv = powf(1.0e6f, -(float)(2 * i) / 64.f);
    float a = p * inv;
    float c = cosf(a), sn = sinf(a);
    const float* qr = g_q + (size_t)s * QD + h * HDIM;
    float x1 = qr[i], x2 = qr[i + 32];
    float x1n = x1 * c - x2 * sn;
    float x2n = x2 * c + x1 * sn;
    float x1b = __shfl_down_sync(0xffffffffu, x1n, 1);
    float x2b = __shfl_down_sync(0xffffffffu, x2n, 1);
    if (!(i & 1)) {
        unsigned wh, wl;
        size_t w1 = (size_t)s * (QD / 2) + h * 32 + (i >> 1);
        pack_planes(x1n, x1b, wh, wl);
        g_qp[0][w1] = wh; g_qp[1][w1] = wl;
        pack_planes(x2n, x2b, wh, wl);
        g_qp[0][w1 + 16] = wh; g_qp[1][w1 + 16] = wl;
    }
}

// ---------------- RoPE: k fp32 -> ktp packed transposed [kvh][d2][t] ----------------
__global__ void rope_k_kernel(const int* __restrict__ pos) {
    int s = blockIdx.x;
    int kvh = threadIdx.x >> 5, i = threadIdx.x & 31;
    float p = (float)pos[s];
    float inv = powf(1.0e6f, -(float)(2 * i) / 64.f);
    float a = p * inv;
    float c = cosf(a), sn = sinf(a);
    const float* kr = g_k + (size_t)s * KD + kvh * HDIM;
    float x1 = kr[i], x2 = kr[i + 32];
    float x1n = x1 * c - x2 * sn;
    float x2n = x2 * c + x1 * sn;
    float x1b = __shfl_down_sync(0xffffffffu, x1n, 1);
    float x2b = __shfl_down_sync(0xffffffffu, x2n, 1);
    if (!(i & 1)) {
        unsigned wh, wl;
        size_t w1 = (size_t)kvh * 32 * NTOK + (size_t)(i >> 1) * NTOK + s;
        pack_planes(x1n, x1b, wh, wl);
        g_ktp[0][w1] = wh; g_ktp[1][w1] = wl;
        size_t w2 = w1 + (size_t)16 * NTOK;
        pack_planes(x2n, x2b, wh, wl);
        g_ktp[0][w2] = wh; g_ktp[1][w2] = wl;
    }
}

// ---------------- repack V: fp32 [t][kvh*64+d] -> vtp [kvh][t2][d] ----------------
__global__ void repack_v_kernel() {
    int w = blockIdx.x * 256 + threadIdx.x;   // over NKV*1024*64
    int kvh = w >> 16;
    int rem = w & 65535;
    int t2 = rem >> 6;
    int d = rem & 63;
    float a = g_v[(size_t)(2 * t2) * KD + kvh * HDIM + d];
    float b = g_v[(size_t)(2 * t2 + 1) * KD + kvh * HDIM + d];
    unsigned wh, wl;
    pack_planes(a, b, wh, wl);
    g_vtp[0][w] = wh;
    g_vtp[1][w] = wl;
}

// ---------------- softmax: scores row -> P packed ----------------
__global__ void softmax_kernel() {
    int q = blockIdx.x, h = blockIdx.y;
    int tid = threadIdx.x;
    const float* s = g_scores + ((size_t)h * NTOK + q) * NTOK;
    int n = q + 1;
    __shared__ float sh[8];
    // max
    float m = -1e30f;
    for (int i = tid; i < n; i += 256) m = fmaxf(m, s[i]);
    for (int o = 16; o > 0; o >>= 1) m = fmaxf(m, __shfl_xor_sync(0xffffffffu, m, o));
    if ((tid & 31) == 0) sh[tid >> 5] = m;
    __syncthreads();
    m = -1e30f;
    for (int k = 0; k < 8; k++) m = fmaxf(m, sh[k]);
    __syncthreads();
    // sum
    float sum = 0.f;
    for (int i = tid; i < n; i += 256) sum += expf((s[i] - m) * 0.125f);
    for (int o = 16; o > 0; o >>= 1) sum += __shfl_xor_sync(0xffffffffu, sum, o);
    if ((tid & 31) == 0) sh[tid >> 5] = sum;
    __syncthreads();
    sum = 0.f;
    for (int k = 0; k < 8; k++) sum += sh[k];
    float rinv = 1.f / sum;
    size_t base = ((size_t)h * NTOK + q) * (NTOK / 2);
    for (int t2 = tid; t2 < NTOK / 2; t2 += 256) {
        int t0 = 2 * t2;
        float p0 = (t0 < n) ? expf((s[t0] - m) * 0.125f) * rinv : 0.f;
        float p1 = (t0 + 1 < n) ? expf((s[t0 + 1] - m) * 0.125f) * rinv : 0.f;
        unsigned wh, wl;
        pack_planes(p0, p1, wh, wl);
        g_pp[0][base + t2] = wh;
        g_pp[1][base + t2] = wl;
    }
}

// ---------------- router ----------------
__global__ void router_kernel(const float* __restrict__ Wr) {
    int t = blockIdx.x;
    int wid = threadIdx.x >> 5, lane = threadIdx.x & 31;
    __shared__ float logits[NE];
    const float* x = g_hn2f + (size_t)t * DMODEL;
    float s = 0.f;
    for (int d = lane; d < DMODEL; d += 32) s += x[d] * Wr[d * NE + wid];
    for (int o = 16; o > 0; o >>= 1) s += __shfl_xor_sync(0xffffffffu, s, o);
    if (lane == 0) logits[wid] = s;
    __syncthreads();
    if (threadIdx.x == 0) {
        float m = -1e30f;
        for (int e = 0; e < NE; e++) m = fmaxf(m, logits[e]);
        float p[NE], sum = 0.f;
        for (int e = 0; e < NE; e++) { p[e] = expf(logits[e] - m); sum += p[e]; }
        for (int e = 0; e < NE; e++) p[e] /= sum;
        int i1 = 0;
        for (int e = 1; e < NE; e++) if (p[e] > p[i1]) i1 = e;
        int i2 = (i1 == 0) ? 1 : 0;
        for (int e = 0; e < NE; e++) if (e != i1 && p[e] > p[i2]) i2 = e;
        float v1 = p[i1], v2 = p[i2], tot = v1 + v2;
        v1 /= tot; v2 /= tot;
        for (int e = 0; e < NE; e++) g_comb[t * NE + e] = 0.f;
        g_comb[t * NE + i1] = v1;
        g_comb[t * NE + i2] = v2;
        int pos1 = atomicAdd(&g_cnt[i1], 1); g_idx[i1 * NTOK + pos1] = t;
        int pos2 = atomicAdd(&g_cnt[i2], 1); g_idx[i2 * NTOK + pos2] = t;
        g_tokexp[t * 2 + 0] = i1; g_tokpos[t * 2 + 0] = pos1;
        g_tokexp[t * 2 + 1] = i2; g_tokpos[t * 2 + 1] = pos2;
    }
}

__global__ void zero_cnt_kernel() {
    if (threadIdx.x < NE) g_cnt[threadIdx.x] = 0;
}

__global__ void scan_kernel() {
    if (threadIdx.x == 0) {
        int s = 0;
        for (int e = 0; e < NE; e++) { g_off[e] = s; s += g_cnt[e]; }
    }
}

// ---------------- silu(gate)*up -> packed actcp ----------------
__global__ void silu_mul_kernel() {
    size_t i = ((size_t)blockIdx.x * 256 + threadIdx.x) * 4;
    float4 g = *(float4*)&g_act[i];
    float4 u = *(float4*)&g_act2[i];
    float a0 = (g.x / (1.f + expf(-g.x))) * u.x;
    float a1 = (g.y / (1.f + expf(-g.y))) * u.y;
    float a2 = (g.z / (1.f + expf(-g.z))) * u.z;
    float a3 = (g.w / (1.f + expf(-g.w))) * u.w;
    unsigned wh0, wl0, wh1, wl1;
    pack_planes(a0, a1, wh0, wl0);
    pack_planes(a2, a3, wh1, wl1);
    size_t w = i >> 1;
    g_actcp[0][w] = wh0; g_actcp[0][w + 1] = wh1;
    g_actcp[1][w] = wl0; g_actcp[1][w + 1] = wl1;
}

// ---------------- combine ----------------
__global__ void combine_kernel(float* __restrict__ out) {
    int t = blockIdx.x;
    int e0 = g_tokexp[t * 2 + 0], e1 = g_tokexp[t * 2 + 1];
    size_t r0 = (size_t)(g_off[e0] + g_tokpos[t * 2 + 0]) * DMODEL;
    size_t r1 = (size_t)(g_off[e1] + g_tokpos[t * 2 + 1]) * DMODEL;
    float w0 = g_comb[t * NE + e0], w1 = g_comb[t * NE + e1];
    size_t base = (size_t)t * DMODEL;
    for (int d = threadIdx.x * 4; d < DMODEL; d += 256 * 4) {
        float4 h = *(float4*)&g_h1[base + d];
        float4 d0 = *(float4*)&g_downc[r0 + d];
        float4 d1 = *(float4*)&g_downc[r1 + d];
        h.x += w0 * d0.x + w1 * d1.x;
        h.y += w0 * d0.y + w1 * d1.y;
        h.z += w0 * d0.z + w1 * d1.z;
        h.w += w0 * d0.w + w1 * d1.w;
        *(float4*)&out[base + d] = h;
    }
}

// ---------------- host ----------------
static void* sym_addr(const void* symbol) {
    void* p = nullptr;
    cudaGetSymbolAddress(&p, symbol);
    return p;
}

extern "C" void kernel_launch(void* const* d_in, const int* in_sizes, int n_in,
                              void* d_out, int out_size) {
    const float* hid = (const float*)d_in[0];
    const int*   pos = (const int*)d_in[1];
    const float* ln1 = (const float*)d_in[2];
    const float* Wq  = (const float*)d_in[3];
    const float* Wk  = (const float*)d_in[4];
    const float* Wv  = (const float*)d_in[5];
    const float* Wo  = (const float*)d_in[6];
    const float* ln2 = (const float*)d_in[7];
    const float* Wr  = (const float*)d_in[8];
    const float* W1  = (const float*)d_in[9];
    const float* W3  = (const float*)d_in[10];
    const float* W2  = (const float*)d_in[11];
    float* out = (float*)d_out;

    unsigned* wqp0 = (unsigned*)sym_addr(g_wqp);
    unsigned* wkp0 = (unsigned*)sym_addr(g_wkp);
    unsigned* wvp0 = (unsigned*)sym_addr(g_wvp);
    unsigned* wop0 = (unsigned*)sym_addr(g_wop);
    unsigned* w1p0 = (unsigned*)sym_addr(g_w1p);
    unsigned* w3p0 = (unsigned*)sym_addr(g_w3p);
    unsigned* w2p0 = (unsigned*)sym_addr(g_w2p);
    unsigned* hnp0 = (unsigned*)sym_addr(g_hnp);
    unsigned* hn2p0= (unsigned*)sym_addr(g_hn2p);
    float* hn2f    = (float*)sym_addr(g_hn2f);

    const size_t WQN = (size_t)(DMODEL / 2) * QD;
    const size_t WKN = (size_t)(DMODEL / 2) * KD;
    const size_t WON = (size_t)(QD / 2) * DMODEL;
    const size_t W1N = (size_t)NE * (DMODEL / 2) * FF;
    const size_t W2N = (size_t)NE * (FF / 2) * DMODEL;

    // 0) split weights into fp16 hi/lo planes
    split_kernel<<<dim3(QD / 256, DMODEL / 2), 256>>>(Wq, wqp0, wqp0 + WQN, QD);
    split_kernel<<<dim3(KD / 256, DMODEL / 2), 256>>>(Wk, wkp0, wkp0 + WKN, KD);
    split_kernel<<<dim3(KD / 256, DMODEL / 2), 256>>>(Wv, wvp0, wvp0 + WKN, KD);
    split_kernel<<<dim3(DMODEL / 256, QD / 2), 256>>>(Wo, wop0, wop0 + WON, DMODEL);
    split_kernel<<<dim3(FF / 256, NE * DMODEL / 2), 256>>>(W1, w1p0, w1p0 + W1N, FF);
    split_kernel<<<dim3(FF / 256, NE * DMODEL / 2), 256>>>(W3, w3p0, w3p0 + W1N, FF);
    split_kernel<<<dim3(DMODEL / 256, NE * FF / 2), 256>>>(W2, w2p0, w2p0 + W2N, DMODEL);

    // 1) rmsnorm1 -> hnp
    rmsnorm_kernel<false><<<NTOK, 256>>>(hid, ln1, hnp0, hnp0 + NTOK * DMODEL / 2, nullptr);
    // 2) QKV -> fp32 q,k,v
    gemmv2<0><<<dim3(24, NTOK / 128), 256>>>(nullptr);
    // 3) RoPE -> packed q / transposed-packed k ; repack v
    rope_q_kernel<<<NTOK, NH * 32>>>(pos);
    rope_k_kernel<<<NTOK, NKV * 32>>>(pos);
    repack_v_kernel<<<(NKV * (NTOK / 2) * HDIM) / 256, 256>>>();
    // 4) attention: S = QK^T (causal skip) ; softmax -> P ; PV -> attn packed
    gemmv2<4><<<dim3(NTOK / 128, NTOK / 128, NH), 256>>>(nullptr);
    softmax_kernel<<<dim3(NTOK, NH), 256>>>();
    gemmv2<5><<<dim3(1, NTOK / 128, NH), 256>>>(nullptr);
    // 5) O projection + residual -> h1
    gemmv2<1><<<dim3(DMODEL / 128, NTOK / 128), 256>>>(hid);
    // 6) rmsnorm2 -> hn2p + fp32
    rmsnorm_kernel<true><<<NTOK, 256>>>((const float*)sym_addr(g_h1), ln2,
                                        hn2p0, hn2p0 + NTOK * DMODEL / 2, hn2f);
    // 7) router
    zero_cnt_kernel<<<1, 32>>>();
    router_kernel<<<NTOK, 256>>>(Wr);
    scan_kernel<<<1, 32>>>();
    // 8) MoE gate+up (all experts, one launch)
    gemmv2<2><<<dim3(112, NTOK / 128, NE), 256>>>(nullptr);
    // 9) silu*up -> packed actcp
    silu_mul_kernel<<<(NROWS * FF) / (256 * 4), 256>>>();
    // 10) MoE down (all experts, one launch)
    gemmv2<3><<<dim3(DMODEL / 128, NTOK / 128, NE), 256>>>(nullptr);
    // 11) combine
    combine_kernel<<<NTOK, 256>>>(out);
}

// round 9
// speedup vs baseline: 1.2276x; 1.2276x over previous
#include <cuda_runtime.h>
#include <cuda_fp16.h>
#include <math.h>

#define NTOK 2048
#define DMODEL 2048
#define NH 32
#define NKV 8
#define HDIM 64
#define QD 2048
#define KD 512
#define NE 8
#define FF 7168
#define NROWS (2 * NTOK)
#define RMS_EPS 1e-5f

// ---------------- scratch (device globals) ----------------
__device__ unsigned g_hnp [2][NTOK * DMODEL / 2];
__device__ unsigned g_hn2p[2][NTOK * DMODEL / 2];
__device__ float    g_hn2f[NTOK * DMODEL];
__device__ float    g_q   [NTOK * QD];
__device__ float    g_k   [NTOK * KD];
__device__ float    g_v   [NTOK * KD];
__device__ unsigned g_qp  [2][NTOK * QD / 2];
__device__ unsigned g_ktp [2][NKV * (HDIM / 2) * NTOK];
__device__ unsigned g_vtp [2][NKV * (NTOK / 2) * HDIM];
__device__ float    g_scores[134217728];                 // [h][q][t]
__device__ unsigned g_pp  [2][67108864];                 // [h][q][t2] unnormalized exp
__device__ float    g_lsum[NH * NTOK];
__device__ unsigned g_attnp[2][NTOK * QD / 2];
__device__ float    g_h1  [NTOK * DMODEL];
__device__ float    g_comb[NTOK * NE];
__device__ int      g_cnt [NE];
__device__ int      g_off [NE];
__device__ int      g_idx [NE * NTOK];
__device__ int      g_tokexp[NTOK * 2];
__device__ int      g_tokpos[NTOK * 2];
__device__ float    g_act [NROWS * FF];
__device__ float    g_act2[NROWS * FF];
__device__ unsigned g_actcp[2][NROWS * FF / 2];
__device__ float    g_downc[NROWS * DMODEL];
// packed weights
__device__ unsigned g_wqp[2][(DMODEL / 2) * QD];
__device__ unsigned g_wkp[2][(DMODEL / 2) * KD];
__device__ unsigned g_wvp[2][(DMODEL / 2) * KD];
__device__ unsigned g_wop[2][(QD / 2) * DMODEL];
__device__ unsigned g_w1p[2][NE * (DMODEL / 2) * FF];
__device__ unsigned g_w3p[2][NE * (DMODEL / 2) * FF];
__device__ unsigned g_w2p[2][NE * (FF / 2) * DMODEL];

// ---------------- helpers ----------------
__device__ __forceinline__ void pack_planes(float a, float b, unsigned& wh, unsigned& wl) {
    __half ha = __float2half_rn(a), hb = __float2half_rn(b);
    __half la = __float2half_rn(a - __half2float(ha));
    __half lb = __float2half_rn(b - __half2float(hb));
    wh = (unsigned)__half_as_ushort(ha) | ((unsigned)__half_as_ushort(hb) << 16);
    wl = (unsigned)__half_as_ushort(la) | ((unsigned)__half_as_ushort(lb) << 16);
}

__device__ __forceinline__ void mma_f16(float* c, const unsigned* a, const unsigned* b) {
    asm volatile(
        "mma.sync.aligned.m16n8k16.row.col.f32.f16.f16.f32 "
        "{%0,%1,%2,%3}, {%4,%5,%6,%7}, {%8,%9}, {%0,%1,%2,%3};"
        : "+f"(c[0]), "+f"(c[1]), "+f"(c[2]), "+f"(c[3])
        : "r"(a[0]), "r"(a[1]), "r"(a[2]), "r"(a[3]), "r"(b[0]), "r"(b[1]));
}

#define CP16(dst, src, sz) \
    asm volatile("cp.async.cg.shared.global [%0], [%1], 16, %2;" :: "r"(dst), "l"(src), "r"(sz))
#define CPCOMMIT() asm volatile("cp.async.commit_group;")
#define CPWAIT2()  asm volatile("cp.async.wait_group 2;")

// ---------------- vectorized weight split ----------------
__global__ void split4_kernel(const float* __restrict__ in, unsigned* __restrict__ oh,
                              unsigned* __restrict__ ol, int C) {
    int w4 = blockIdx.x * 256 + threadIdx.x;
    int C4 = C >> 2;
    int r2 = w4 / C4;
    int c = (w4 - r2 * C4) * 4;
    float4 a = *(const float4*)&in[(size_t)(2 * r2) * C + c];
    float4 b = *(const float4*)&in[(size_t)(2 * r2 + 1) * C + c];
    uint4 H, L;
    pack_planes(a.x, b.x, H.x, L.x);
    pack_planes(a.y, b.y, H.y, L.y);
    pack_planes(a.z, b.z, H.z, L.z);
    pack_planes(a.w, b.w, H.w, L.w);
    *(uint4*)&oh[(size_t)r2 * C + c] = H;
    *(uint4*)&ol[(size_t)r2 * C + c] = L;
}

// ---------------- unified fp16x3 GEMM with cp.async 4-stage pipeline ----------------
// SMEM (dynamic): A = 4 stg x 2 planes x 128 rows x 8 words (swizzled); B = 4 x 2 x 8 x 136
// MODE 0 QKV / 1 O+res / 2 MoE gate-up / 3 MoE down / 4 S=QK^T / 5 PV (scaled by 1/lsum)
template <int MODE>
__global__ void __launch_bounds__(256)
gemmv2(const float* __restrict__ Rres) {
    const int by = blockIdx.y;
    const int bz = blockIdx.z;

    const unsigned* Ah;
    const unsigned* Al;
    const unsigned* Bh;
    const unsigned* Bl;
    float* Cf = nullptr;
    int N, K, rsA, ncol0 = blockIdx.x * 128, cnt = 0, off = 0;

    if (MODE == 0) {
        Ah = g_hnp[0]; Al = g_hnp[1]; rsA = DMODEL / 2; K = DMODEL;
        if (blockIdx.x < 16)      { Bh = g_wqp[0]; Bl = g_wqp[1]; Cf = g_q; N = QD; }
        else if (blockIdx.x < 20) { Bh = g_wkp[0]; Bl = g_wkp[1]; Cf = g_k; N = KD; ncol0 = (blockIdx.x - 16) * 128; }
        else                      { Bh = g_wvp[0]; Bl = g_wvp[1]; Cf = g_v; N = KD; ncol0 = (blockIdx.x - 20) * 128; }
    } else if (MODE == 1) {
        Ah = g_attnp[0]; Al = g_attnp[1]; rsA = QD / 2; K = QD;
        Bh = g_wop[0]; Bl = g_wop[1]; Cf = g_h1; N = DMODEL;
    } else if (MODE == 2) {
        cnt = g_cnt[bz];
        if (by * 128 >= cnt) return;
        off = g_off[bz];
        Ah = g_hn2p[0]; Al = g_hn2p[1]; rsA = DMODEL / 2; K = DMODEL; N = FF;
        size_t wo = (size_t)bz * (DMODEL / 2) * FF;
        if (blockIdx.x < 56) { Bh = g_w1p[0] + wo; Bl = g_w1p[1] + wo; Cf = g_act; }
        else                 { Bh = g_w3p[0] + wo; Bl = g_w3p[1] + wo; Cf = g_act2; ncol0 = (blockIdx.x - 56) * 128; }
    } else if (MODE == 3) {
        cnt = g_cnt[bz];
        if (by * 128 >= cnt) return;
        off = g_off[bz];
        Ah = g_actcp[0]; Al = g_actcp[1]; rsA = FF / 2; K = FF; N = DMODEL;
        size_t wo = (size_t)bz * (FF / 2) * DMODEL;
        Bh = g_w2p[0] + wo; Bl = g_w2p[1] + wo; Cf = g_downc;
    } else if (MODE == 4) {
        if (ncol0 >= by * 128 + 128) return;   // causal block skip
        Ah = g_qp[0] + bz * (HDIM / 2); Al = g_qp[1] + bz * (HDIM / 2);
        rsA = QD / 2; K = HDIM; N = NTOK;
        size_t wo = (size_t)(bz >> 2) * (HDIM / 2) * NTOK;
        Bh = g_ktp[0] + wo; Bl = g_ktp[1] + wo;
        Cf = g_scores + (size_t)bz * NTOK * NTOK;
    } else {  // MODE 5 PV
        size_t ao = (size_t)bz * NTOK * (NTOK / 2);
        Ah = g_pp[0] + ao; Al = g_pp[1] + ao;
        rsA = NTOK / 2; K = by * 128 + 128; N = HDIM;
        size_t wo = (size_t)(bz >> 2) * (NTOK / 2) * HDIM;
        Bh = g_vtp[0] + wo; Bl = g_vtp[1] + wo;
    }

    extern __shared__ unsigned dynsmem[];       // A: words [0,8192); B: [8192, 16896)
    const unsigned smem0 = (unsigned)__cvta_generic_to_shared(dynsmem);

    const int tid  = threadIdx.x;
    const int lane = tid & 31;
    const int wid  = tid >> 5;
    const int wm = (wid >> 2) * 64;
    const int wn = (wid & 3) * 32;
    const int lr = lane >> 2;
    const int lk = lane & 3;
    const int p4 = (lane & 16) >> 2;            // A-word swizzle for frag reads

    float acc[4][4][4];
#pragma unroll
    for (int i = 0; i < 4; i++)
#pragma unroll
        for (int j = 0; j < 4; j++)
#pragma unroll
            for (int q = 0; q < 4; q++) acc[i][j][q] = 0.f;

    // A loader: 256 thr = 128 rows x 2 k-halves (16B each per plane)
    const int arow = tid & 127;
    const int kh4  = (tid >> 7) * 4;
    size_t aoff;
    {
        int r0 = by * 128 + arow;
        if (MODE == 2) {
            int rr = r0 < cnt ? r0 : cnt - 1;
            aoff = (size_t)g_idx[bz * NTOK + rr] * rsA;
        } else if (MODE == 3) {
            int rr = r0 < cnt ? r0 : cnt - 1;
            aoff = (size_t)(off + rr) * rsA;
        } else {
            aoff = (size_t)r0 * rsA;
        }
    }
    // B loader: 8 k2-rows x 128 n
    const int k2r = tid >> 5;
    const int n4  = lane * 4;
    const int bsz = ((MODE != 5) || (n4 < HDIM)) ? 16 : 0;

    const int niter = K / 16;
    const unsigned aswz = (unsigned)(kh4 ^ (arow & 4));   // store-side swizzle

    auto issue_stage = [&](int s) {
        int buf = s & 3;
        int k2b = s * 8;
        unsigned da = smem0 + ((unsigned)(buf * 2048 + arow * 8) + aswz) * 4u;
        CP16(da,        Ah + aoff + k2b + kh4, 16);
        CP16(da + 4096, Al + aoff + k2b + kh4, 16);      // lo plane (+1024 words)
        size_t boff = (size_t)(k2b + k2r) * N + ncol0 + n4;
        unsigned db = smem0 + (8192u + (unsigned)((buf * 16 + k2r) * 136 + n4)) * 4u;
        CP16(db,        Bh + boff, bsz);
        CP16(db + 4352, Bl + boff, bsz);                 // lo plane (+8*136 words)
    };

    // prologue: stages 0..2
    for (int s = 0; s < 3; s++) {
        if (s < niter) issue_stage(s);
        CPCOMMIT();
    }

    const unsigned* Asm = dynsmem;
    const unsigned* Bsm = dynsmem + 8192;
    const int aw0 = lk ^ p4;

    for (int it = 0; it < niter; it++) {
        CPWAIT2();
        __syncthreads();
        if (it + 3 < niter) issue_stage(it + 3);
        CPCOMMIT();
        const int cur = it & 3;

        unsigned afh[4][4], afl[4][4], bfh[4][2], bfl[4][2];
        const int ab = cur * 2048;
#pragma unroll
        for (int i = 0; i < 4; i++) {
            int b0 = ab + (wm + i * 16 + lr) * 8;
            afh[i][0] = Asm[b0 + aw0];
            afh[i][1] = Asm[b0 + 64 + aw0];
            afh[i][2] = Asm[b0 + (aw0 ^ 4)];
            afh[i][3] = Asm[b0 + 64 + (aw0 ^ 4)];
            afl[i][0] = Asm[b0 + 1024 + aw0];
            afl[i][1] = Asm[b0 + 1088 + aw0];
            afl[i][2] = Asm[b0 + 1024 + (aw0 ^ 4)];
            afl[i][3] = Asm[b0 + 1088 + (aw0 ^ 4)];
        }
        const int bb = cur * 16 * 136;
#pragma unroll
        for (int j = 0; j < 4; j++) {
            int c = wn + j * 8 + lr;
            bfh[j][0] = Bsm[bb + lk * 136 + c];
            bfh[j][1] = Bsm[bb + (lk + 4) * 136 + c];
            bfl[j][0] = Bsm[bb + 1088 + lk * 136 + c];
            bfl[j][1] = Bsm[bb + 1088 + (lk + 4) * 136 + c];
        }
#pragma unroll
        for (int i = 0; i < 4; i++)
#pragma unroll
            for (int j = 0; j < 4; j++) {
                mma_f16(acc[i][j], afl[i], bfh[j]);
                mma_f16(acc[i][j], afh[i], bfl[j]);
                mma_f16(acc[i][j], afh[i], bfh[j]);
            }
    }

    // ---- epilogue ----
#pragma unroll
    for (int i = 0; i < 4; i++) {
#pragma unroll
        for (int j = 0; j < 4; j++) {
            int cc = ncol0 + wn + j * 8 + lk * 2;
#pragma unroll
            for (int half = 0; half < 2; half++) {
                int rg = by * 128 + wm + i * 16 + lr + half * 8;
                float v0 = acc[i][j][half * 2 + 0];
                float v1 = acc[i][j][half * 2 + 1];
                if (MODE == 0) {
                    *(float2*)&Cf[(size_t)rg * N + cc] = make_float2(v0, v1);
                } else if (MODE == 1) {
                    size_t o = (size_t)rg * N + cc;
                    *(float2*)&Cf[o] = make_float2(v0 + Rres[o], v1 + Rres[o + 1]);
                } else if (MODE == 2) {
                    if (rg < cnt)
                        *(float2*)&Cf[(size_t)(off + rg) * FF + cc] = make_float2(v0, v1);
                } else if (MODE == 3) {
                    if (rg < cnt)
                        *(float2*)&Cf[(size_t)(off + rg) * DMODEL + cc] = make_float2(v0, v1);
                } else if (MODE == 4) {
                    *(float2*)&Cf[(size_t)rg * NTOK + cc] = make_float2(v0, v1);
                } else {  // PV: scale by 1/l, pack
                    if (cc < HDIM) {
                        float rinv = 1.0f / g_lsum[(size_t)bz * NTOK + rg];
                        unsigned wh, wl;
                        pack_planes(v0 * rinv, v1 * rinv, wh, wl);
                        size_t w = (size_t)rg * (QD / 2) + bz * (HDIM / 2) + (cc >> 1);
                        g_attnp[0][w] = wh;
                        g_attnp[1][w] = wl;
                    }
                }
            }
        }
    }
}

// ---------------- rmsnorm -> packed planes (+ optional fp32) ----------------
template <bool F32>
__global__ void rmsnorm_kernel(const float* __restrict__ x, const float* __restrict__ w,
                               unsigned* __restrict__ oh, unsigned* __restrict__ ol,
                               float* __restrict__ of) {
    int row = blockIdx.x;
    int tid = threadIdx.x;
    const float2* xr = (const float2*)(x + (size_t)row * DMODEL);
    float s = 0.f;
    for (int i = tid; i < DMODEL / 2; i += 256) {
        float2 v = xr[i];
        s += v.x * v.x + v.y * v.y;
    }
    for (int o = 16; o > 0; o >>= 1) s += __shfl_xor_sync(0xffffffffu, s, o);
    __shared__ float sh[8];
    if ((tid & 31) == 0) sh[tid >> 5] = s;
    __syncthreads();
    float tot = 0.f;
    for (int k = 0; k < 8; k++) tot += sh[k];
    float inv = rsqrtf(tot / (float)DMODEL + RMS_EPS);
    for (int i = tid; i < DMODEL / 2; i += 256) {
        float2 v = xr[i];
        float y0 = v.x * inv * w[2 * i];
        float y1 = v.y * inv * w[2 * i + 1];
        unsigned wh, wl;
        pack_planes(y0, y1, wh, wl);
        oh[(size_t)row * (DMODEL / 2) + i] = wh;
        ol[(size_t)row * (DMODEL / 2) + i] = wl;
        if (F32) *(float2*)&of[(size_t)row * DMODEL + 2 * i] = make_float2(y0, y1);
    }
}

// ---------------- RoPE q -> packed ----------------
__global__ void rope_q_kernel(const int* __restrict__ pos) {
    int s = blockIdx.x;
    int h = threadIdx.x >> 5, i = threadIdx.x & 31;
    float p = (float)pos[s];
    float inv = powf(1.0e6f, -(float)(2 * i) / 64.f);
    float a = p * inv;
    float c = cosf(a), sn = sinf(a);
    const float* qr = g_q + (size_t)s * QD + h * HDIM;
    float x1 = qr[i], x2 = qr[i + 32];
    float x1n = x1 * c - x2 * sn;
    float x2n = x2 * c + x1 * sn;
    float x1b = __shfl_down_sync(0xffffffffu, x1n, 1);
    float x2b = __shfl_down_sync(0xffffffffu, x2n, 1);
    if (!(i & 1)) {
        unsigned wh, wl;
        size_t w1 = (size_t)s * (QD / 2) + h * 32 + (i >> 1);
        pack_planes(x1n, x1b, wh, wl);
        g_qp[0][w1] = wh; g_qp[1][w1] = wl;
        pack_planes(x2n, x2b, wh, wl);
        g_qp[0][w1 + 16] = wh; g_qp[1][w1 + 16] = wl;
    }
}

// ---------------- RoPE k -> packed transposed [kvh][d2][t] ----------------
__global__ void rope_k_kernel(const int* __restrict__ pos) {
    int s = blockIdx.x;
    int kvh = threadIdx.x >> 5, i = threadIdx.x & 31;
    float p = (float)pos[s];
    float inv = powf(1.0e6f, -(float)(2 * i) / 64.f);
    float a = p * inv;
    float c = cosf(a), sn = sinf(a);
    const float* kr = g_k + (size_t)s * KD + kvh * HDIM;
    float x1 = kr[i], x2 = kr[i + 32];
    float x1n = x1 * c - x2 * sn;
    float x2n = x2 * c + x1 * sn;
    float x1b = __shfl_down_sync(0xffffffffu, x1n, 1);
    float x2b = __shfl_down_sync(0xffffffffu, x2n, 1);
    if (!(i & 1)) {
        unsigned wh, wl;
        size_t w1 = (size_t)kvh * 32 * NTOK + (size_t)(i >> 1) * NTOK + s;
        pack_planes(x1n, x1b, wh, wl);
        g_ktp[0][w1] = wh; g_ktp[1][w1] = wl;
        size_t w2 = w1 + (size_t)16 * NTOK;
        pack_planes(x2n, x2b, wh, wl);
        g_ktp[0][w2] = wh; g_ktp[1][w2] = wl;
    }
}

// ---------------- repack V -> [kvh][t2][d] ----------------
__global__ void repack_v_kernel() {
    int w = blockIdx.x * 256 + threadIdx.x;
    int kvh = w >> 16;
    int rem = w & 65535;
    int t2 = rem >> 6;
    int d = rem & 63;
    float a = g_v[(size_t)(2 * t2) * KD + kvh * HDIM + d];
    float b = g_v[(size_t)(2 * t2 + 1) * KD + kvh * HDIM + d];
    unsigned wh, wl;
    pack_planes(a, b, wh, wl);
    g_vtp[0][w] = wh;
    g_vtp[1][w] = wl;
}

// ---------------- softmax: raw scores -> unnormalized exp (packed) + row sum ----------------
__global__ void softmax_kernel() {
    int q = blockIdx.x, h = blockIdx.y;
    int tid = threadIdx.x;
    const float* s = g_scores + ((size_t)h * NTOK + q) * NTOK;
    int n = q + 1;
    int kend2 = (((q >> 7) + 1) << 7) >> 1;   // zero-fill to PV block end
    __shared__ float sh[8];
    float m = -1e30f;
    for (int i = tid; i < n; i += 256) m = fmaxf(m, s[i]);
    for (int o = 16; o > 0; o >>= 1) m = fmaxf(m, __shfl_xor_sync(0xffffffffu, m, o));
    if ((tid & 31) == 0) sh[tid >> 5] = m;
    __syncthreads();
    m = -1e30f;
    for (int k = 0; k < 8; k++) m = fmaxf(m, sh[k]);
    __syncthreads();
    float sum = 0.f;
    size_t base = ((size_t)h * NTOK + q) * (NTOK / 2);
    for (int t2 = tid; t2 < kend2; t2 += 256) {
        int t0 = 2 * t2;
        float e0 = (t0 < n) ? expf((s[t0] - m) * 0.125f) : 0.f;
        float e1 = (t0 + 1 < n) ? expf((s[t0 + 1] - m) * 0.125f) : 0.f;
        sum += e0 + e1;
        unsigned wh, wl;
        pack_planes(e0, e1, wh, wl);
        g_pp[0][base + t2] = wh;
        g_pp[1][base + t2] = wl;
    }
    for (int o = 16; o > 0; o >>= 1) sum += __shfl_xor_sync(0xffffffffu, sum, o);
    if ((tid & 31) == 0) sh[tid >> 5] = sum;
    __syncthreads();
    if (tid == 0) {
        float tot = 0.f;
        for (int k = 0; k < 8; k++) tot += sh[k];
        g_lsum[h * NTOK + q] = tot;
    }
}

// ---------------- router ----------------
__global__ void router_kernel(const float* __restrict__ Wr) {
    int t = blockIdx.x;
    int wid = threadIdx.x >> 5, lane = threadIdx.x & 31;
    __shared__ float logits[NE];
    const float* x = g_hn2f + (size_t)t * DMODEL;
    float s = 0.f;
    for (int d = lane; d < DMODEL; d += 32) s += x[d] * Wr[d * NE + wid];
    for (int o = 16; o > 0; o >>= 1) s += __shfl_xor_sync(0xffffffffu, s, o);
    if (lane == 0) logits[wid] = s;
    __syncthreads();
    if (threadIdx.x == 0) {
        float m = -1e30f;
        for (int e = 0; e < NE; e++) m = fmaxf(m, logits[e]);
        float p[NE], sum = 0.f;
        for (int e = 0; e < NE; e++) { p[e] = expf(logits[e] - m); sum += p[e]; }
        for (int e = 0; e < NE; e++) p[e] /= sum;
        int i1 = 0;
        for (int e = 1; e < NE; e++) if (p[e] > p[i1]) i1 = e;
        int i2 = (i1 == 0) ? 1 : 0;
        for (int e = 0; e < NE; e++) if (e != i1 && p[e] > p[i2]) i2 = e;
        float v1 = p[i1], v2 = p[i2], tot = v1 + v2;
        v1 /= tot; v2 /= tot;
        for (int e = 0; e < NE; e++) g_comb[t * NE + e] = 0.f;
        g_comb[t * NE + i1] = v1;
        g_comb[t * NE + i2] = v2;
        int pos1 = atomicAdd(&g_cnt[i1], 1); g_idx[i1 * NTOK + pos1] = t;
        int pos2 = atomicAdd(&g_cnt[i2], 1); g_idx[i2 * NTOK + pos2] = t;
        g_tokexp[t * 2 + 0] = i1; g_tokpos[t * 2 + 0] = pos1;
        g_tokexp[t * 2 + 1] = i2; g_tokpos[t * 2 + 1] = pos2;
    }
}

__global__ void zero_cnt_kernel() {
    if (threadIdx.x < NE) g_cnt[threadIdx.x] = 0;
}

__global__ void scan_kernel() {
    if (threadIdx.x == 0) {
        int s = 0;
        for (int e = 0; e < NE; e++) { g_off[e] = s; s += g_cnt[e]; }
    }
}

// ---------------- silu(gate)*up -> packed actcp ----------------
__global__ void silu_mul_kernel() {
    size_t i = ((size_t)blockIdx.x * 256 + threadIdx.x) * 4;
    float4 g = *(float4*)&g_act[i];
    float4 u = *(float4*)&g_act2[i];
    float a0 = (g.x / (1.f + expf(-g.x))) * u.x;
    float a1 = (g.y / (1.f + expf(-g.y))) * u.y;
    float a2 = (g.z / (1.f + expf(-g.z))) * u.z;
    float a3 = (g.w / (1.f + expf(-g.w))) * u.w;
    unsigned wh0, wl0, wh1, wl1;
    pack_planes(a0, a1, wh0, wl0);
    pack_planes(a2, a3, wh1, wl1);
    size_t w = i >> 1;
    g_actcp[0][w] = wh0; g_actcp[0][w + 1] = wh1;
    g_actcp[1][w] = wl0; g_actcp[1][w + 1] = wl1;
}

// ---------------- combine ----------------
__global__ void combine_kernel(float* __restrict__ out) {
    int t = blockIdx.x;
    int e0 = g_tokexp[t * 2 + 0], e1 = g_tokexp[t * 2 + 1];
    size_t r0 = (size_t)(g_off[e0] + g_tokpos[t * 2 + 0]) * DMODEL;
    size_t r1 = (size_t)(g_off[e1] + g_tokpos[t * 2 + 1]) * DMODEL;
    float w0 = g_comb[t * NE + e0], w1 = g_comb[t * NE + e1];
    size_t base = (size_t)t * DMODEL;
    for (int d = threadIdx.x * 4; d < DMODEL; d += 256 * 4) {
        float4 h = *(float4*)&g_h1[base + d];
        float4 d0 = *(float4*)&g_downc[r0 + d];
        float4 d1 = *(float4*)&g_downc[r1 + d];
        h.x += w0 * d0.x + w1 * d1.x;
        h.y += w0 * d0.y + w1 * d1.y;
        h.z += w0 * d0.z + w1 * d1.z;
        h.w += w0 * d0.w + w1 * d1.w;
        *(float4*)&out[base + d] = h;
    }
}

// ---------------- host ----------------
static void* sym_addr(const void* symbol) {
    void* p = nullptr;
    cudaGetSymbolAddress(&p, symbol);
    return p;
}

extern "C" void kernel_launch(void* const* d_in, const int* in_sizes, int n_in,
                              void* d_out, int out_size) {
    const float* hid = (const float*)d_in[0];
    const int*   pos = (const int*)d_in[1];
    const float* ln1 = (const float*)d_in[2];
    const float* Wq  = (const float*)d_in[3];
    const float* Wk  = (const float*)d_in[4];
    const float* Wv  = (const float*)d_in[5];
    const float* Wo  = (const float*)d_in[6];
    const float* ln2 = (const float*)d_in[7];
    const float* Wr  = (const float*)d_in[8];
    const float* W1  = (const float*)d_in[9];
    const float* W3  = (const float*)d_in[10];
    const float* W2  = (const float*)d_in[11];
    float* out = (float*)d_out;

    unsigned* wqp0 = (unsigned*)sym_addr(g_wqp);
    unsigned* wkp0 = (unsigned*)sym_addr(g_wkp);
    unsigned* wvp0 = (unsigned*)sym_addr(g_wvp);
    unsigned* wop0 = (unsigned*)sym_addr(g_wop);
    unsigned* w1p0 = (unsigned*)sym_addr(g_w1p);
    unsigned* w3p0 = (unsigned*)sym_addr(g_w3p);
    unsigned* w2p0 = (unsigned*)sym_addr(g_w2p);
    unsigned* hnp0 = (unsigned*)sym_addr(g_hnp);
    unsigned* hn2p0= (unsigned*)sym_addr(g_hn2p);
    float* hn2f    = (float*)sym_addr(g_hn2f);

    const size_t WQN = (size_t)(DMODEL / 2) * QD;
    const size_t WKN = (size_t)(DMODEL / 2) * KD;
    const size_t WON = (size_t)(QD / 2) * DMODEL;
    const size_t W1N = (size_t)NE * (DMODEL / 2) * FF;
    const size_t W2N = (size_t)NE * (FF / 2) * DMODEL;

    const int SMEMB = 16896 * 4;   // 67,584 B dynamic SMEM for gemmv2
    cudaFuncSetAttribute(gemmv2<0>, cudaFuncAttributeMaxDynamicSharedMemorySize, SMEMB);
    cudaFuncSetAttribute(gemmv2<1>, cudaFuncAttributeMaxDynamicSharedMemorySize, SMEMB);
    cudaFuncSetAttribute(gemmv2<2>, cudaFuncAttributeMaxDynamicSharedMemorySize, SMEMB);
    cudaFuncSetAttribute(gemmv2<3>, cudaFuncAttributeMaxDynamicSharedMemorySize, SMEMB);
    cudaFuncSetAttribute(gemmv2<4>, cudaFuncAttributeMaxDynamicSharedMemorySize, SMEMB);
    cudaFuncSetAttribute(gemmv2<5>, cudaFuncAttributeMaxDynamicSharedMemorySize, SMEMB);

    // 0) split weights into fp16 hi/lo planes (vectorized)
    split4_kernel<<<(int)(WQN / 1024), 256>>>(Wq, wqp0, wqp0 + WQN, QD);
    split4_kernel<<<(int)(WKN / 1024), 256>>>(Wk, wkp0, wkp0 + WKN, KD);
    split4_kernel<<<(int)(WKN / 1024), 256>>>(Wv, wvp0, wvp0 + WKN, KD);
    split4_kernel<<<(int)(WON / 1024), 256>>>(Wo, wop0, wop0 + WON, DMODEL);
    split4_kernel<<<(int)(W1N / 1024), 256>>>(W1, w1p0, w1p0 + W1N, FF);
    split4_kernel<<<(int)(W1N / 1024), 256>>>(W3, w3p0, w3p0 + W1N, FF);
    split4_kernel<<<(int)(W2N / 1024), 256>>>(W2, w2p0, w2p0 + W2N, DMODEL);

    // 1) rmsnorm1 -> hnp
    rmsnorm_kernel<false><<<NTOK, 256>>>(hid, ln1, hnp0, hnp0 + NTOK * DMODEL / 2, nullptr);
    // 2) QKV
    gemmv2<0><<<dim3(24, NTOK / 128), 256, SMEMB>>>(nullptr);
    // 3) RoPE + V repack
    rope_q_kernel<<<NTOK, NH * 32>>>(pos);
    rope_k_kernel<<<NTOK, NKV * 32>>>(pos);
    repack_v_kernel<<<(NKV * (NTOK / 2) * HDIM) / 256, 256>>>();
    // 4) attention: S -> softmax(unnormalized) -> PV (scaled)
    gemmv2<4><<<dim3(NTOK / 128, NTOK / 128, NH), 256, SMEMB>>>(nullptr);
    softmax_kernel<<<dim3(NTOK, NH), 256>>>();
    gemmv2<5><<<dim3(1, NTOK / 128, NH), 256, SMEMB>>>(nullptr);
    // 5) O projection + residual
    gemmv2<1><<<dim3(DMODEL / 128, NTOK / 128), 256, SMEMB>>>(hid);
    // 6) rmsnorm2
    rmsnorm_kernel<true><<<NTOK, 256>>>((const float*)sym_addr(g_h1), ln2,
                                        hn2p0, hn2p0 + NTOK * DMODEL / 2, hn2f);
    // 7) router
    zero_cnt_kernel<<<1, 32>>>();
    router_kernel<<<NTOK, 256>>>(Wr);
    scan_kernel<<<1, 32>>>();
    // 8) MoE gate+up
    gemmv2<2><<<dim3(112, NTOK / 128, NE), 256, SMEMB>>>(nullptr);
    // 9) silu*up -> packed
    silu_mul_kernel<<<(NROWS * FF) / (256 * 4), 256>>>();
    // 10) MoE down
    gemmv2<3><<<dim3(DMODEL / 128, NTOK / 128, NE), 256, SMEMB>>>(nullptr);
    // 11) combine
    combine_kernel<<<NTOK, 256>>>(out);
}